// round 1
// baseline (speedup 1.0000x reference)
#include <cuda_runtime.h>
#include <cstdint>

typedef unsigned long long ull;

#define KKn  9
#define Bn   8
#define Cn   256
#define Hn   96
#define Wn   96
#define On   256
#define HWn  (Hn*Wn)          // 9216
#define KDIM (Cn*KKn)         // 2304
#define TP   24               // pixels per tile in main kernel
#define SROW (KDIM + 4)       // padded smem row (2308 floats)
#define SMEM_BYTES (TP*SROW*4 + 3*TP*KKn*4)

// ---------------- scratch (device globals; no allocation allowed) ----------------
__device__ float g_xt[Bn*HWn*Cn];        // x transposed to NHWC (75.5 MB)
__device__ float g_py [Bn*KKn*HWn];      // absolute sample y coords
__device__ float g_px [Bn*KKn*HWn];      // absolute sample x coords
__device__ float g_msk[Bn*KKn*HWn];      // sigmoid(mask)
__device__ float g_wsoff[Cn*KKn*28];     // offset-conv weights [c][k][28-padded oc]
__device__ float g_wt2[On*KDIM];         // main weights [o][k*256+c]
__device__ float g_bnA[On];              // folded BN scale
__device__ float g_bnB[On];              // folded BN bias (incl. b_dcn)

// ---------------- f32x2 helpers (FFMA2: full-rate fp32 on sm_103a) ----------------
__device__ __forceinline__ ull pk2(float a, float b) {
    ull r; asm("mov.b64 %0, {%1, %2};" : "=l"(r) : "f"(a), "f"(b)); return r;
}
__device__ __forceinline__ void unpk(ull v, float& a, float& b) {
    asm("mov.b64 {%0, %1}, %2;" : "=f"(a), "=f"(b) : "l"(v));
}
__device__ __forceinline__ void fma2(ull& d, ull a, ull b) {
    asm("fma.rn.f32x2 %0, %1, %2, %0;" : "+l"(d) : "l"(a), "l"(b));
}

// ---------------- prep: weight re-layouts + BN fold ----------------
__global__ void prep_kernel(const float* __restrict__ w_off,
                            const float* __restrict__ w_dcn,
                            const float* __restrict__ b_dcn,
                            const float* __restrict__ gamma,
                            const float* __restrict__ beta,
                            const float* __restrict__ rmean,
                            const float* __restrict__ rvar) {
    int t = blockIdx.x * blockDim.x + threadIdx.x;
    int stride = gridDim.x * blockDim.x;
    for (int i = t; i < Cn*KKn*28; i += stride) {
        int oc = i % 28; int rest = i / 28;
        int kk = rest % KKn; int c = rest / KKn;
        g_wsoff[i] = (oc < 27) ? w_off[(oc*Cn + c)*KKn + kk] : 0.f;
    }
    for (int i = t; i < On*KDIM; i += stride) {
        int K = i % KDIM; int o = i / KDIM;
        int kk = K / Cn;  int c = K % Cn;
        g_wt2[i] = w_dcn[(o*Cn + c)*KKn + kk];
    }
    if (t < On) {
        float inv = rsqrtf(rvar[t] + 1e-5f);
        float A = gamma[t] * inv;
        g_bnA[t] = A;
        g_bnB[t] = (b_dcn[t] - rmean[t]) * A + beta[t];
    }
}

// ---------------- NCHW -> NHWC transpose ----------------
__global__ void transpose_kernel(const float* __restrict__ x) {
    __shared__ float tile[32][33];
    int bh = blockIdx.z;                       // b*H + h
    int c0 = blockIdx.y * 32;
    int w0 = blockIdx.x * 32;
    int b = bh / Hn; int h = bh % Hn;
    for (int i = threadIdx.y; i < 32; i += 8)
        tile[i][threadIdx.x] = x[((b*Cn + c0 + i)*Hn + h)*Wn + w0 + threadIdx.x];
    __syncthreads();
    for (int i = threadIdx.y; i < 32; i += 8)
        g_xt[((size_t)(b*Hn + h)*Wn + w0 + i)*Cn + c0 + threadIdx.x] = tile[threadIdx.x][i];
}

// ---------------- offset conv: 27ch 3x3 conv -> py/px/mask ----------------
__global__ __launch_bounds__(256) void offset_kernel(const float* __restrict__ x,
                                                     const float* __restrict__ b_off) {
    __shared__ float ws[32*KKn*28];            // 32 c-chunk of weights, 32.25 KB
    int pix = blockIdx.x * 256 + threadIdx.x;
    int b = pix / HWn; int hw = pix % HWn;
    int h = hw / Wn;   int w = hw % Wn;

    ull acc[14];
    #pragma unroll
    for (int q = 0; q < 14; q++) acc[q] = 0ull;

    for (int c0 = 0; c0 < Cn; c0 += 32) {
        __syncthreads();
        for (int i = threadIdx.x; i < 32*KKn*28; i += 256)
            ws[i] = g_wsoff[c0*KKn*28 + i];
        __syncthreads();
        for (int c = 0; c < 32; c++) {
            const float* xr = x + ((size_t)(b*Cn + c0 + c)*Hn)*Wn;
            #pragma unroll
            for (int kk = 0; kk < 9; kk++) {
                int dy = kk/3 - 1, dx = kk%3 - 1;
                int yy = h + dy, xx = w + dx;
                float xv = 0.f;
                if ((unsigned)yy < (unsigned)Hn && (unsigned)xx < (unsigned)Wn)
                    xv = xr[yy*Wn + xx];
                ull xv2 = pk2(xv, xv);
                const ulonglong2* wrow = (const ulonglong2*)(ws + (c*KKn + kk)*28);
                #pragma unroll
                for (int q = 0; q < 7; q++) {
                    ulonglong2 wv = wrow[q];
                    fma2(acc[2*q],   wv.x, xv2);
                    fma2(acc[2*q+1], wv.y, xv2);
                }
            }
        }
    }

    float v[28];
    #pragma unroll
    for (int q = 0; q < 14; q++) unpk(acc[q], v[2*q], v[2*q+1]);

    #pragma unroll
    for (int k = 0; k < 9; k++) {
        int dy = k/3 - 1, dx = k%3 - 1;
        float py = v[2*k]   + b_off[2*k]   + (float)(h + dy);
        float px = v[2*k+1] + b_off[2*k+1] + (float)(w + dx);
        float mv = v[18+k] + b_off[18+k];
        float mm = 1.f / (1.f + expf(-mv));
        int idx = (b*KKn + k)*HWn + hw;
        g_py[idx] = py; g_px[idx] = px; g_msk[idx] = mm;
    }
}

// ---------------- main: fused bilinear sampling + GEMM + BN + ReLU ----------------
__device__ __forceinline__ float4 corner_ld(const float* __restrict__ xtb, int y, int x, int c4) {
    if ((unsigned)y < (unsigned)Hn && (unsigned)x < (unsigned)Wn)
        return *(const float4*)(xtb + ((y*Wn + x) << 8) + (c4 << 2));
    return make_float4(0.f, 0.f, 0.f, 0.f);
}

__global__ __launch_bounds__(256) void main_kernel(float* __restrict__ out) {
    extern __shared__ float smem[];
    float* s   = smem;                 // [TP][SROW]
    float* spy = smem + TP*SROW;       // [TP*9]
    float* spx = spy + TP*KKn;
    float* smk = spx + TP*KKn;

    int tid  = threadIdx.x;
    int pixb = blockIdx.x * TP;
    int b    = pixb / HWn;
    int hwb  = pixb % HWn;

    if (tid < TP*KKn) {
        int p = tid / KKn, k = tid % KKn;
        int gi = (b*KKn + k)*HWn + hwb + p;
        spy[tid] = g_py[gi]; spx[tid] = g_px[gi]; smk[tid] = g_msk[gi];
    }
    __syncthreads();

    // ---- producer: s[p][k*256+c] = bilinear(xt, py, px) * mask ----
    const float* xtb = g_xt + (size_t)b * (HWn*Cn);
    for (int t = tid; t < TP*KKn*64; t += 256) {
        int c4 = t & 63;
        int k  = (t >> 6) % KKn;
        int p  = t / (KKn*64);
        float py = spy[p*KKn + k], px = spx[p*KKn + k], mm = smk[p*KKn + k];
        float fy = floorf(py), fx = floorf(px);
        int y0 = (int)fy, x0 = (int)fx;
        float wy = py - fy, wx = px - fx;
        float4 v00 = corner_ld(xtb, y0,   x0,   c4);
        float4 v01 = corner_ld(xtb, y0,   x0+1, c4);
        float4 v10 = corner_ld(xtb, y0+1, x0,   c4);
        float4 v11 = corner_ld(xtb, y0+1, x0+1, c4);
        float w00 = (1.f-wy)*(1.f-wx), w01 = (1.f-wy)*wx;
        float w10 = wy*(1.f-wx),       w11 = wy*wx;
        float4 r;
        r.x = (v00.x*w00 + v01.x*w01 + v10.x*w10 + v11.x*w11) * mm;
        r.y = (v00.y*w00 + v01.y*w01 + v10.y*w10 + v11.y*w11) * mm;
        r.z = (v00.z*w00 + v01.z*w01 + v10.z*w10 + v11.z*w11) * mm;
        r.w = (v00.w*w00 + v01.w*w01 + v10.w*w10 + v11.w*w11) * mm;
        *(float4*)(s + p*SROW + k*256 + c4*4) = r;
    }
    __syncthreads();

    // ---- consumer: out[o][p] = sum_K wt2[o][K] * s[p][K] (f32x2 k-pairing) ----
    int oo = tid >> 2;        // 0..63 -> 4 o's each
    int po = tid & 3;         // 0..3  -> 6 p's each
    int ob = oo * 4;
    int pb = po * 6;

    ull acc[4][6];
    #pragma unroll
    for (int j = 0; j < 4; j++)
        #pragma unroll
        for (int i = 0; i < 6; i++) acc[j][i] = 0ull;

    const float* wr = g_wt2 + (size_t)ob * KDIM;
    const float* sp = s + pb * SROW;

    #pragma unroll 2
    for (int k = 0; k < KDIM; k += 4) {
        ulonglong2 wv[4];
        #pragma unroll
        for (int j = 0; j < 4; j++)
            wv[j] = *(const ulonglong2*)(wr + j*KDIM + k);
        #pragma unroll
        for (int i = 0; i < 6; i++) {
            ulonglong2 sv = *(const ulonglong2*)(sp + i*SROW + k);
            #pragma unroll
            for (int j = 0; j < 4; j++) {
                fma2(acc[j][i], wv[j].x, sv.x);
                fma2(acc[j][i], wv[j].y, sv.y);
            }
        }
    }

    // ---- epilogue: BN fold + ReLU ----
    #pragma unroll
    for (int j = 0; j < 4; j++) {
        int o = ob + j;
        float A = g_bnA[o], Bb = g_bnB[o];
        float* orow = out + (size_t)(b*On + o)*HWn + hwb;
        #pragma unroll
        for (int i = 0; i < 6; i++) {
            float lo, hi; unpk(acc[j][i], lo, hi);
            float r = (lo + hi) * A + Bb;
            orow[pb + i] = fmaxf(r, 0.f);
        }
    }
}

// ---------------- launch ----------------
extern "C" void kernel_launch(void* const* d_in, const int* in_sizes, int n_in,
                              void* d_out, int out_size) {
    const float* x      = (const float*)d_in[0];
    const float* w_off  = (const float*)d_in[1];
    const float* b_off  = (const float*)d_in[2];
    const float* w_dcn  = (const float*)d_in[3];
    const float* b_dcn  = (const float*)d_in[4];
    const float* gamma  = (const float*)d_in[5];
    const float* beta   = (const float*)d_in[6];
    const float* rmean  = (const float*)d_in[7];
    const float* rvar   = (const float*)d_in[8];
    float* out = (float*)d_out;

    cudaFuncSetAttribute(main_kernel, cudaFuncAttributeMaxDynamicSharedMemorySize, SMEM_BYTES);

    prep_kernel<<<256, 256>>>(w_off, w_dcn, b_dcn, gamma, beta, rmean, rvar);

    dim3 tgrid(Wn/32, Cn/32, Bn*Hn);
    transpose_kernel<<<tgrid, dim3(32, 8)>>>(x);

    offset_kernel<<<(Bn*HWn)/256, 256>>>(x, b_off);

    main_kernel<<<(Bn*HWn)/TP, 256, SMEM_BYTES>>>(out);
}